// round 14
// baseline (speedup 1.0000x reference)
#include <cuda_runtime.h>
#include <cuda_bf16.h>
#include <cstdint>

// Problem constants
#define BB 2
#define HH 192
#define WW 192
#define CC 192
#define WS 16
#define SHIFT 8
#define NH 6
#define HD 32
#define NTOK 256          // tokens per window
#define NWSIDE 12         // windows per side
#define NWB 144           // windows per batch
#define NWIN 288          // total windows
#define QK_SCALE 0.17677669529663687f  // 32^-0.5

// ---- mma / ldmatrix helpers ----
__device__ __forceinline__ uint32_t smem_u32(const void* p) {
    return (uint32_t)__cvta_generic_to_shared(p);
}
__device__ __forceinline__ void ldsm_x2(uint32_t& r0, uint32_t& r1, uint32_t addr) {
    asm volatile("ldmatrix.sync.aligned.m8n8.x2.shared.b16 {%0,%1}, [%2];"
                 : "=r"(r0), "=r"(r1) : "r"(addr));
}
__device__ __forceinline__ void ldsm_x2_t(uint32_t& r0, uint32_t& r1, uint32_t addr) {
    asm volatile("ldmatrix.sync.aligned.m8n8.x2.trans.shared.b16 {%0,%1}, [%2];"
                 : "=r"(r0), "=r"(r1) : "r"(addr));
}
__device__ __forceinline__ void ldsm_x4(uint32_t* r, uint32_t addr) {
    asm volatile("ldmatrix.sync.aligned.m8n8.x4.shared.b16 {%0,%1,%2,%3}, [%4];"
                 : "=r"(r[0]), "=r"(r[1]), "=r"(r[2]), "=r"(r[3]) : "r"(addr));
}
__device__ __forceinline__ void mma_bf16(float* c, const uint32_t* a, const uint32_t* b) {
    asm volatile("mma.sync.aligned.m16n8k16.row.col.f32.bf16.bf16.f32 "
                 "{%0,%1,%2,%3},{%4,%5,%6,%7},{%8,%9},{%0,%1,%2,%3};"
                 : "+f"(c[0]), "+f"(c[1]), "+f"(c[2]), "+f"(c[3])
                 : "r"(a[0]), "r"(a[1]), "r"(a[2]), "r"(a[3]), "r"(b[0]), "r"(b[1]));
}
__device__ __forceinline__ uint32_t bf2(float x, float y) {
    __nv_bfloat162 t = __floats2bfloat162_rn(x, y);   // .x = x (low half)
    return *(uint32_t*)&t;
}
__device__ __forceinline__ void split_pack(float x, float y, uint32_t& hi, uint32_t& lo) {
    __nv_bfloat16 hx = __float2bfloat16(x), hy = __float2bfloat16(y);
    __nv_bfloat162 h2 = __halves2bfloat162(hx, hy);
    hi = *(uint32_t*)&h2;
    lo = bf2(x - __bfloat162float(hx), y - __bfloat162float(hy));
}
// ---- cp.async helpers ----
__device__ __forceinline__ void cp16(uint32_t dst, const void* src) {
    asm volatile("cp.async.ca.shared.global [%0], [%1], 16;" :: "r"(dst), "l"(src));
}
__device__ __forceinline__ void cp_commit() { asm volatile("cp.async.commit_group;"); }
__device__ __forceinline__ void cp_wait1() { asm volatile("cp.async.wait_group 1;" ::: "memory"); }
__device__ __forceinline__ void cp_wait0() { asm volatile("cp.async.wait_group 0;" ::: "memory"); }

// Scratch (static __device__ globals)
__device__ float g_cth[NWIN * NTOK];
__device__ float g_ctv[NWIN * NTOK];
__device__ __nv_bfloat16 g_owh[(size_t)NWIN * NTOK * CC];  // attn out hi
__device__ __nv_bfloat16 g_owl[(size_t)NWIN * NTOK * CC];  // attn out lo
__device__ __nv_bfloat16 g_Wh[CC * CC];                    // proj_w hi
__device__ __nv_bfloat16 g_Wl[CC * CC];                    // proj_w lo

__device__ __forceinline__ int wrapH(int hs) { int h = hs + SHIFT; return (h >= HH) ? h - HH : h; }

// ---------------------------------------------------------------------------
// Kernel 0: split proj_w into bf16 hi/lo
// ---------------------------------------------------------------------------
__global__ void __launch_bounds__(256) wprep_kernel(const float* __restrict__ proj_w) {
    int idx = blockIdx.x * 256 + threadIdx.x;
    if (idx < CC * CC) {
        float v = proj_w[idx];
        __nv_bfloat16 h = __float2bfloat16(v);
        g_Wh[idx] = h;
        g_Wl[idx] = __float2bfloat16(v - __bfloat162float(h));
    }
}

// ---------------------------------------------------------------------------
// Kernel 1: per-window geo cumulative tables cth/ctv (unchanged)
// ---------------------------------------------------------------------------
__global__ void __launch_bounds__(256) geo_kernel(const float* __restrict__ x,
                                                  const float* __restrict__ geo_sigma) {
    int win = blockIdx.x;
    int b = win / NWB, wr = (win % NWB) / NWSIDE, wc = win % NWSIDE;
    int tid = threadIdx.x;

    __shared__ float dh[16][16];
    __shared__ float dv[16][16];

    float sigma = fabsf(geo_sigma[0]);

    for (int p = tid; p < 480; p += 256) {
        int r0, c0, r1, c1; bool isH = (p < 240);
        if (isH) { int r = p / 15, j = p % 15; r0 = r; c0 = j; r1 = r; c1 = j + 1; }
        else     { int pp = p - 240; int i = pp / 16, c = pp % 16; r0 = i; c0 = c; r1 = i + 1; c1 = c; }
        int h0 = wrapH(wr * WS + r0), w0 = wrapH(wc * WS + c0);
        int h1 = wrapH(wr * WS + r1), w1 = wrapH(wc * WS + c1);
        const float* a  = x + ((size_t)((b * HH + h0) * WW + w0)) * CC;
        const float* bb = x + ((size_t)((b * HH + h1) * WW + w1)) * CC;
        float s = 0.f;
        #pragma unroll 4
        for (int ch = 0; ch < CC; ch += 4) {
            float4 av = *(const float4*)(a + ch);
            float4 bv = *(const float4*)(bb + ch);
            s += fabsf(bv.x - av.x) + fabsf(bv.y - av.y) + fabsf(bv.z - av.z) + fabsf(bv.w - av.w);
        }
        if (isH) dh[r0][c0] = s; else dv[r0][c0] = s;
    }
    __syncthreads();

    if (tid < 16) {
        int r = tid; float acc = 0.f;
        g_cth[win * NTOK + r * 16 + 0] = 0.f;
        for (int c = 1; c < 16; c++) {
            acc += 1.f + sigma * dh[r][c - 1];
            g_cth[win * NTOK + r * 16 + c] = acc;
        }
    } else if (tid < 32) {
        int c = tid - 16; float acc = 0.f;
        g_ctv[win * NTOK + 0 * 16 + c] = 0.f;
        for (int r = 1; r < 16; r++) {
            acc += 1.f + sigma * dv[r - 1][c];
            g_ctv[win * NTOK + r * 16 + c] = acc;
        }
    }
}

// ---------------------------------------------------------------------------
// Kernel 2: attention, 512 threads / block, warp = 16 q-rows.
// mma.sync bf16 hi/lo split; light epilogue (geo_h & ctv[gi] precomputed,
// geo_v shared across the two q-rows, mask templated out for uniform windows).
// ---------------------------------------------------------------------------
#define KV_STRIDE 40
#define SMEM2_BYTES (4 * 256 * KV_STRIDE * 2 + (964 + 256 + 256 + 256) * 4)

__device__ __forceinline__ const float* q_row_ptr(const float* qkv, int b, int wr, int wc,
                                                  int t, int head) {
    int i = t >> 4, j = t & 15;
    int h = wrapH(wr * WS + i), w = wrapH(wc * WS + j);
    return qkv + ((size_t)((b * HH + h) * WW + w)) * (3 * CC) + head * HD;
}

template<bool MIXED>
__global__ void __launch_bounds__(512, 1) attn_kernel_t(const float* __restrict__ qkv,
                                                        const float* __restrict__ rpb_table,
                                                        const float* __restrict__ geo_scale) {
    extern __shared__ char smem_raw[];
    __nv_bfloat16* Kh = (__nv_bfloat16*)smem_raw;              // [256][40]
    __nv_bfloat16* Kl = Kh + 256 * KV_STRIDE;
    __nv_bfloat16* Vh = Kl + 256 * KV_STRIDE;
    __nv_bfloat16* Vl = Vh + 256 * KV_STRIDE;
    float* rpb_sh = (float*)(smem_raw + 4 * 256 * KV_STRIDE * 2);  // [961] pad 964
    float* cth_sh = rpb_sh + 964;
    float* ctv_sh = cth_sh + 256;
    int*   reg_sh = (int*)(ctv_sh + 256);

    int win = blockIdx.x, head = blockIdx.y;
    int b = win / NWB, wr = (win % NWB) / NWSIDE, wc = win % NWSIDE;
    int tid = threadIdx.x;

    // ---- fill K/V hi/lo: 2 threads per token (16 dims each) ----
    {
        int t = tid >> 1;
        int d0 = (tid & 1) * 16;
        int i = t >> 4, j = t & 15;
        int h = wrapH(wr * WS + i), w = wrapH(wc * WS + j);
        const float* base = qkv + ((size_t)((b * HH + h) * WW + w)) * (3 * CC) + head * HD;
        const float* kp = base + CC + d0;
        const float* vp = base + 2 * CC + d0;
        #pragma unroll
        for (int d = 0; d < 16; d++) {
            float kv = kp[d];
            __nv_bfloat16 khv = __float2bfloat16(kv);
            Kh[t * KV_STRIDE + d0 + d] = khv;
            Kl[t * KV_STRIDE + d0 + d] = __float2bfloat16(kv - __bfloat162float(khv));
            float vv = vp[d];
            __nv_bfloat16 vhv = __float2bfloat16(vv);
            Vh[t * KV_STRIDE + d0 + d] = vhv;
            Vl[t * KV_STRIDE + d0 + d] = __float2bfloat16(vv - __bfloat162float(vhv));
        }
    }
    for (int u = tid; u < 961; u += 512) rpb_sh[u] = rpb_table[u * NH + head];
    if (tid < 256) {
        int i = tid >> 4, j = tid & 15;
        int hs = wr * WS + i, ws = wc * WS + j;
        cth_sh[tid] = g_cth[win * NTOK + tid];
        ctv_sh[tid] = g_ctv[win * NTOK + tid];
        if (MIXED) {
            int rh  = (hs < HH - WS) ? 0 : ((hs < HH - SHIFT) ? 1 : 2);
            int rw2 = (ws < WW - WS) ? 0 : ((ws < WW - SHIFT) ? 1 : 2);
            reg_sh[tid] = rh * 3 + rw2;
        }
    }

    int warp = tid >> 5, lane = tid & 31;
    int g = lane >> 2, t4 = lane & 3;
    int R = warp * 16;

    // ---- Q fragments (scale folded, hi/lo split) ----
    uint32_t qfh[2][4], qfl[2][4];
    {
        const float* p0 = q_row_ptr(qkv, b, wr, wc, R + g, head);
        const float* p1 = q_row_ptr(qkv, b, wr, wc, R + g + 8, head);
        #pragma unroll
        for (int ks = 0; ks < 2; ks++) {
            int kc = ks * 16 + 2 * t4;
            float2 v;
            v = *(const float2*)(p0 + kc);
            split_pack(v.x * QK_SCALE, v.y * QK_SCALE, qfh[ks][0], qfl[ks][0]);
            v = *(const float2*)(p1 + kc);
            split_pack(v.x * QK_SCALE, v.y * QK_SCALE, qfh[ks][1], qfl[ks][1]);
            v = *(const float2*)(p0 + kc + 8);
            split_pack(v.x * QK_SCALE, v.y * QK_SCALE, qfh[ks][2], qfl[ks][2]);
            v = *(const float2*)(p1 + kc + 8);
            split_pack(v.x * QK_SCALE, v.y * QK_SCALE, qfh[ks][3], qfl[ks][3]);
        }
    }
    __syncthreads();

    // ---- per-thread epilogue precompute ----
    float gsc = geo_scale[head];
    float cthq0 = cth_sh[R + g], cthq1 = cth_sh[R + g + 8];
    int mr_q0 = 0, mr_q1 = 0;
    if (MIXED) { mr_q0 = reg_sh[R + g]; mr_q1 = reg_sh[R + g + 8]; }
    // 4 distinct key-columns per thread: ck(m) = (m>>1)*8 + 2*t4 + (m&1)
    float fq0[4], fq1[4], cgv[4];
    #pragma unroll
    for (int m = 0; m < 4; m++) {
        int ck = (m >> 1) * 8 + 2 * t4 + (m & 1);
        float cv = cth_sh[R + ck];
        fq0[m] = fabsf(cv - cthq0);
        fq1[m] = fabsf(cv - cthq1);
        cgv[m] = ctv_sh[R + ck];
    }

    float o[4][4];
    #pragma unroll
    for (int dn = 0; dn < 4; dn++)
        #pragma unroll
        for (int e = 0; e < 4; e++) o[dn][e] = 0.f;
    float lsum0 = 0.f, lsum1 = 0.f;

    int lrow = lane & 7, lhi = (lane >> 3) & 1;

    #pragma unroll 1
    for (int T = 0; T < 8; T++) {
        int kb = T * 32;
        uint32_t pf_h[2][4], pf_l[2][4];

        #pragma unroll
        for (int nt = 0; nt < 4; nt++) {
            // K fragments for this 8-key group
            uint32_t kfh[2][2], kfl[2][2];
            int row = kb + nt * 8 + lrow;
            #pragma unroll
            for (int ks = 0; ks < 2; ks++) {
                int eoff = ks * 16 + 8 * lhi;
                ldsm_x2(kfh[ks][0], kfh[ks][1], smem_u32(&Kh[row * KV_STRIDE + eoff]));
                ldsm_x2(kfl[ks][0], kfl[ks][1], smem_u32(&Kl[row * KV_STRIDE + eoff]));
            }
            float c[4] = {0.f, 0.f, 0.f, 0.f};
            #pragma unroll
            for (int ks = 0; ks < 2; ks++) {
                mma_bf16(c, qfh[ks], kfh[ks]);
                mma_bf16(c, qfh[ks], kfl[ks]);
                mma_bf16(c, qfl[ks], kfh[ks]);
            }
            // epilogue
            int rk = (kb >> 4) + (nt >> 1);
            int rowoff = (warp - rk + 15) * 31 + 15;
            int ck0 = (nt & 1) * 8 + 2 * t4;
            int k0 = kb + nt * 8 + 2 * t4;
            int m0 = (nt & 1) * 2;

            float gv0 = fabsf(ctv_sh[k0]     - cgv[m0]);
            float gv1 = fabsf(ctv_sh[k0 + 1] - cgv[m0 + 1]);
            float s0 = fmaf(-gsc, fq0[m0]     + gv0, c[0] + rpb_sh[rowoff + g - ck0]);
            float s1 = fmaf(-gsc, fq0[m0 + 1] + gv1, c[1] + rpb_sh[rowoff + g - ck0 - 1]);
            float s2 = fmaf(-gsc, fq1[m0]     + gv0, c[2] + rpb_sh[rowoff + g + 8 - ck0]);
            float s3 = fmaf(-gsc, fq1[m0 + 1] + gv1, c[3] + rpb_sh[rowoff + g + 8 - ck0 - 1]);
            if (MIXED) {
                int mr0 = reg_sh[k0], mr1 = reg_sh[k0 + 1];
                s0 += (mr_q0 == mr0) ? 0.f : -100.f;
                s1 += (mr_q0 == mr1) ? 0.f : -100.f;
                s2 += (mr_q1 == mr0) ? 0.f : -100.f;
                s3 += (mr_q1 == mr1) ? 0.f : -100.f;
            }
            float p0 = __expf(s0), p1 = __expf(s1);
            float p2 = __expf(s2), p3 = __expf(s3);
            lsum0 += p0 + p1;
            lsum1 += p2 + p3;

            __nv_bfloat16 h0 = __float2bfloat16(p0), h1 = __float2bfloat16(p1);
            __nv_bfloat16 h2 = __float2bfloat16(p2), h3 = __float2bfloat16(p3);
            int kt = nt >> 1, off = (nt & 1) * 2;
            __nv_bfloat162 hp01 = __halves2bfloat162(h0, h1);
            __nv_bfloat162 hp23 = __halves2bfloat162(h2, h3);
            pf_h[kt][off]     = *(uint32_t*)&hp01;
            pf_h[kt][off + 1] = *(uint32_t*)&hp23;
            pf_l[kt][off]     = bf2(p0 - __bfloat162float(h0), p1 - __bfloat162float(h1));
            pf_l[kt][off + 1] = bf2(p2 - __bfloat162float(h2), p3 - __bfloat162float(h3));
        }

        // AV: O += Ph*Vh + Ph*Vl + Pl*Vh
        #pragma unroll
        for (int dn = 0; dn < 4; dn++)
            #pragma unroll
            for (int kt = 0; kt < 2; kt++) {
                int key = kb + kt * 16 + lrow + 8 * lhi;
                uint32_t vh[2], vl[2];
                ldsm_x2_t(vh[0], vh[1], smem_u32(&Vh[key * KV_STRIDE + dn * 8]));
                ldsm_x2_t(vl[0], vl[1], smem_u32(&Vl[key * KV_STRIDE + dn * 8]));
                mma_bf16(o[dn], pf_h[kt], vh);
                mma_bf16(o[dn], pf_h[kt], vl);
                mma_bf16(o[dn], pf_l[kt], vh);
            }
    }

    // reduce l across the 4 threads sharing each row
    lsum0 += __shfl_xor_sync(0xFFFFFFFF, lsum0, 1);
    lsum0 += __shfl_xor_sync(0xFFFFFFFF, lsum0, 2);
    lsum1 += __shfl_xor_sync(0xFFFFFFFF, lsum1, 1);
    lsum1 += __shfl_xor_sync(0xFFFFFFFF, lsum1, 2);

    // normalize + store as bf16 hi/lo
    float inv0 = 1.f / lsum0;
    float inv1 = 1.f / lsum1;
    size_t i0 = (size_t)win * (NTOK * CC) + (R + g) * CC + head * HD + 2 * t4;
    size_t i1 = (size_t)win * (NTOK * CC) + (R + g + 8) * CC + head * HD + 2 * t4;
    #pragma unroll
    for (int dn = 0; dn < 4; dn++) {
        uint32_t hi, lo;
        split_pack(o[dn][0] * inv0, o[dn][1] * inv0, hi, lo);
        *(uint32_t*)(g_owh + i0 + dn * 8) = hi;
        *(uint32_t*)(g_owl + i0 + dn * 8) = lo;
        split_pack(o[dn][2] * inv1, o[dn][3] * inv1, hi, lo);
        *(uint32_t*)(g_owh + i1 + dn * 8) = hi;
        *(uint32_t*)(g_owl + i1 + dn * 8) = lo;
    }
}

// ---------------------------------------------------------------------------
// Kernel 3: projection via mma.sync bf16 hi/lo split + cp.async double-buffered
// W staging. Block = 64 tokens x 192 outs; 8 warps = 4(m) x 2(n).
// ---------------------------------------------------------------------------
#define AST 200
#define WST 24
#define WBUF (192 * WST)
#define SMEM3_BYTES ((2 * 64 * AST + 4 * WBUF) * 2)

__global__ void __launch_bounds__(256) proj_kernel(const float* __restrict__ proj_b,
                                                   float* __restrict__ out) {
    extern __shared__ char smem3[];
    __nv_bfloat16* Ah = (__nv_bfloat16*)smem3;          // [64][AST]
    __nv_bfloat16* Al = Ah + 64 * AST;
    __nv_bfloat16* Wsh = Al + 64 * AST;                 // [2][192][WST]
    __nv_bfloat16* Wsl = Wsh + 2 * WBUF;                // [2][192][WST]

    int t = threadIdx.x;
    int tok0 = blockIdx.x * 64;

    // Stage A tile (plain stores)
    for (int e = t; e < 64 * 96; e += 256) {
        int row = e / 96, c2 = (e % 96) * 2;
        size_t gidx = (size_t)(tok0 + row) * CC + c2;
        *(uint32_t*)&Ah[row * AST + c2] = *(const uint32_t*)(g_owh + gidx);
        *(uint32_t*)&Al[row * AST + c2] = *(const uint32_t*)(g_owl + gidx);
    }

    // Issue W chunk 0 via cp.async into buffer 0
    #pragma unroll
    for (int e = t; e < 768; e += 256) {
        bool isLo = e >= 384;
        int e2 = isLo ? e - 384 : e;
        int row = e2 >> 1, part = e2 & 1;
        const __nv_bfloat16* src = (isLo ? g_Wl : g_Wh) + row * CC + part * 8;
        __nv_bfloat16* dst = (isLo ? Wsl : Wsh) + row * WST + part * 8;
        cp16(smem_u32(dst), src);
    }
    cp_commit();

    int warp = t >> 5, lane = t & 31;
    int mw = warp & 3, nw = warp >> 2;
    int g = lane >> 2, t4 = lane & 3;
    int lg = lane >> 3;

    float acc[12][4];
    #pragma unroll
    for (int nt = 0; nt < 12; nt++)
        #pragma unroll
        for (int e = 0; e < 4; e++) acc[nt][e] = 0.f;

    int a_row = mw * 16 + (lane & 7) + (lg & 1) * 8;
    int a_col = (lg >> 1) * 8;
    int w_lrow = (lane & 7) + (lg >> 1) * 8;
    int w_col = (lg & 1) * 8;

    #pragma unroll 1
    for (int kc = 0; kc < 12; kc++) {
        __syncthreads();   // A visible (kc=0); prior compute done before buffer reuse
        if (kc + 1 < 12) {
            int buf = (kc + 1) & 1;
            #pragma unroll
            for (int e = t; e < 768; e += 256) {
                bool isLo = e >= 384;
                int e2 = isLo ? e - 384 : e;
                int row = e2 >> 1, part = e2 & 1;
                const __nv_bfloat16* src = (isLo ? g_Wl : g_Wh) + row * CC + (kc + 1) * 16 + part * 8;
                __nv_bfloat16* dst = (isLo ? Wsl : Wsh) + buf * WBUF + row * WST + part * 8;
                cp16(smem_u32(dst), src);
            }
            cp_commit();
            cp_wait1();
        } else {
            cp_wait0();
        }
        __syncthreads();

        const __nv_bfloat16* Wh_c = Wsh + (kc & 1) * WBUF;
        const __nv_bfloat16* Wl_c = Wsl + (kc & 1) * WBUF;

        uint32_t af_h[4], af_l[4];
        ldsm_x4(af_h, smem_u32(&Ah[a_row * AST + kc * 16 + a_col]));
        ldsm_x4(af_l, smem_u32(&Al[a_row * AST + kc * 16 + a_col]));

        uint32_t wf_h[12][2], wf_l[12][2];
        #pragma unroll
        for (int nt2 = 0; nt2 < 6; nt2++) {
            int nbase = nw * 96 + nt2 * 16;
            uint32_t r4[4];
            ldsm_x4(r4, smem_u32(&Wh_c[(nbase + w_lrow) * WST + w_col]));
            wf_h[2 * nt2][0] = r4[0]; wf_h[2 * nt2][1] = r4[1];
            wf_h[2 * nt2 + 1][0] = r4[2]; wf_h[2 * nt2 + 1][1] = r4[3];
            ldsm_x4(r4, smem_u32(&Wl_c[(nbase + w_lrow) * WST + w_col]));
            wf_l[2 * nt2][0] = r4[0]; wf_l[2 * nt2][1] = r4[1];
            wf_l[2 * nt2 + 1][0] = r4[2]; wf_l[2 * nt2 + 1][1] = r4[3];
        }

        #pragma unroll
        for (int nt = 0; nt < 12; nt++) {
            mma_bf16(acc[nt], af_h, wf_h[nt]);
            mma_bf16(acc[nt], af_h, wf_l[nt]);
            mma_bf16(acc[nt], af_l, wf_h[nt]);
        }
    }

    // Epilogue: bias + window-reverse + roll-back scatter
    #pragma unroll
    for (int half = 0; half < 2; half++) {
        int tok = tok0 + mw * 16 + g + half * 8;
        int win = tok >> 8, tt = tok & 255;
        int b = win / NWB, wr = (win % NWB) / NWSIDE, wc = win % NWSIDE;
        int i = tt >> 4, jj = tt & 15;
        int h = wrapH(wr * WS + i), w = wrapH(wc * WS + jj);
        float* op = out + ((size_t)b * (HH * WW) + h * WW + w) * CC;
        #pragma unroll
        for (int nt = 0; nt < 12; nt++) {
            int co = nw * 96 + nt * 8 + 2 * t4;
            float2 r;
            r.x = acc[nt][2 * half + 0] + __ldg(proj_b + co);
            r.y = acc[nt][2 * half + 1] + __ldg(proj_b + co + 1);
            *(float2*)(op + co) = r;
        }
    }
}

// ---------------------------------------------------------------------------
// Launch. Mixed-mask windows (wr==11 || wc==11) get the MIXED attn variant.
// ---------------------------------------------------------------------------
extern "C" void kernel_launch(void* const* d_in, const int* in_sizes, int n_in,
                              void* d_out, int out_size) {
    const float* x        = (const float*)d_in[0];
    const float* qkv      = (const float*)d_in[1];
    const float* rpb      = (const float*)d_in[2];
    const float* gscale   = (const float*)d_in[3];
    const float* gsigma   = (const float*)d_in[4];
    const float* proj_w   = (const float*)d_in[5];
    const float* proj_b   = (const float*)d_in[6];
    float* out            = (float*)d_out;

    cudaFuncSetAttribute(attn_kernel_t<true>,  cudaFuncAttributeMaxDynamicSharedMemorySize, SMEM2_BYTES);
    cudaFuncSetAttribute(attn_kernel_t<false>, cudaFuncAttributeMaxDynamicSharedMemorySize, SMEM2_BYTES);
    cudaFuncSetAttribute(proj_kernel, cudaFuncAttributeMaxDynamicSharedMemorySize, SMEM3_BYTES);

    wprep_kernel<<<(CC * CC + 255) / 256, 256>>>(proj_w);
    geo_kernel<<<NWIN, 256>>>(x, gsigma);
    // MIXED template covers every window (mask only nonzero for wr/wc==11, but
    // reg_sh compare is exact there and zero-cost correct elsewhere); still
    // dispatch both variants so 121/144 windows skip mask work entirely.
    // Grid is all windows; pick variant per launch by splitting is complex with
    // 2D window indexing, so: launch MIXED for all (correct), since per-window
    // split would need a remap. Instead use the cheap uniform variant only when
    // the whole grid qualifies — it doesn't, so launch MIXED for correctness.
    attn_kernel_t<true><<<dim3(NWIN, NH), 512, SMEM2_BYTES>>>(qkv, rpb, gscale);
    proj_kernel<<<(NWIN * NTOK) / 64, 256, SMEM3_BYTES>>>(proj_b, out);
}

// round 15
// speedup vs baseline: 1.3609x; 1.3609x over previous
#include <cuda_runtime.h>
#include <cuda_bf16.h>
#include <cstdint>

// Problem constants
#define BB 2
#define HH 192
#define WW 192
#define CC 192
#define WS 16
#define SHIFT 8
#define NH 6
#define HD 32
#define NTOK 256          // tokens per window
#define NWSIDE 12         // windows per side
#define NWB 144           // windows per batch
#define NWIN 288          // total windows
#define QK_SCALE 0.17677669529663687f  // 32^-0.5

// ---- mma / ldmatrix helpers ----
__device__ __forceinline__ uint32_t smem_u32(const void* p) {
    return (uint32_t)__cvta_generic_to_shared(p);
}
__device__ __forceinline__ void ldsm_x2(uint32_t& r0, uint32_t& r1, uint32_t addr) {
    asm volatile("ldmatrix.sync.aligned.m8n8.x2.shared.b16 {%0,%1}, [%2];"
                 : "=r"(r0), "=r"(r1) : "r"(addr));
}
__device__ __forceinline__ void ldsm_x2_t(uint32_t& r0, uint32_t& r1, uint32_t addr) {
    asm volatile("ldmatrix.sync.aligned.m8n8.x2.trans.shared.b16 {%0,%1}, [%2];"
                 : "=r"(r0), "=r"(r1) : "r"(addr));
}
__device__ __forceinline__ void ldsm_x4(uint32_t* r, uint32_t addr) {
    asm volatile("ldmatrix.sync.aligned.m8n8.x4.shared.b16 {%0,%1,%2,%3}, [%4];"
                 : "=r"(r[0]), "=r"(r[1]), "=r"(r[2]), "=r"(r[3]) : "r"(addr));
}
__device__ __forceinline__ void mma_bf16(float* c, const uint32_t* a, const uint32_t* b) {
    asm volatile("mma.sync.aligned.m16n8k16.row.col.f32.bf16.bf16.f32 "
                 "{%0,%1,%2,%3},{%4,%5,%6,%7},{%8,%9},{%0,%1,%2,%3};"
                 : "+f"(c[0]), "+f"(c[1]), "+f"(c[2]), "+f"(c[3])
                 : "r"(a[0]), "r"(a[1]), "r"(a[2]), "r"(a[3]), "r"(b[0]), "r"(b[1]));
}
__device__ __forceinline__ uint32_t bf2(float x, float y) {
    __nv_bfloat162 t = __floats2bfloat162_rn(x, y);   // .x = x (low half)
    return *(uint32_t*)&t;
}
__device__ __forceinline__ void split_pack(float x, float y, uint32_t& hi, uint32_t& lo) {
    __nv_bfloat16 hx = __float2bfloat16(x), hy = __float2bfloat16(y);
    __nv_bfloat162 h2 = __halves2bfloat162(hx, hy);
    hi = *(uint32_t*)&h2;
    lo = bf2(x - __bfloat162float(hx), y - __bfloat162float(hy));
}

// Scratch (static __device__ globals)
__device__ float g_cth[NWIN * NTOK];
__device__ float g_ctv[NWIN * NTOK];
__device__ __nv_bfloat16 g_owh[(size_t)NWIN * NTOK * CC];  // attn out hi
__device__ __nv_bfloat16 g_owl[(size_t)NWIN * NTOK * CC];  // attn out lo
__device__ __nv_bfloat16 g_Wh[CC * CC];                    // proj_w hi
__device__ __nv_bfloat16 g_Wl[CC * CC];                    // proj_w lo

__device__ __forceinline__ int wrapH(int hs) { int h = hs + SHIFT; return (h >= HH) ? h - HH : h; }

// ---------------------------------------------------------------------------
// Kernel 0: split proj_w into bf16 hi/lo
// ---------------------------------------------------------------------------
__global__ void __launch_bounds__(256) wprep_kernel(const float* __restrict__ proj_w) {
    int idx = blockIdx.x * 256 + threadIdx.x;
    if (idx < CC * CC) {
        float v = proj_w[idx];
        __nv_bfloat16 h = __float2bfloat16(v);
        g_Wh[idx] = h;
        g_Wl[idx] = __float2bfloat16(v - __bfloat162float(h));
    }
}

// ---------------------------------------------------------------------------
// Kernel 1: per-window geo cumulative tables cth/ctv (unchanged)
// ---------------------------------------------------------------------------
__global__ void __launch_bounds__(256) geo_kernel(const float* __restrict__ x,
                                                  const float* __restrict__ geo_sigma) {
    int win = blockIdx.x;
    int b = win / NWB, wr = (win % NWB) / NWSIDE, wc = win % NWSIDE;
    int tid = threadIdx.x;

    __shared__ float dh[16][16];
    __shared__ float dv[16][16];

    float sigma = fabsf(geo_sigma[0]);

    for (int p = tid; p < 480; p += 256) {
        int r0, c0, r1, c1; bool isH = (p < 240);
        if (isH) { int r = p / 15, j = p % 15; r0 = r; c0 = j; r1 = r; c1 = j + 1; }
        else     { int pp = p - 240; int i = pp / 16, c = pp % 16; r0 = i; c0 = c; r1 = i + 1; c1 = c; }
        int h0 = wrapH(wr * WS + r0), w0 = wrapH(wc * WS + c0);
        int h1 = wrapH(wr * WS + r1), w1 = wrapH(wc * WS + c1);
        const float* a  = x + ((size_t)((b * HH + h0) * WW + w0)) * CC;
        const float* bb = x + ((size_t)((b * HH + h1) * WW + w1)) * CC;
        float s = 0.f;
        #pragma unroll 4
        for (int ch = 0; ch < CC; ch += 4) {
            float4 av = *(const float4*)(a + ch);
            float4 bv = *(const float4*)(bb + ch);
            s += fabsf(bv.x - av.x) + fabsf(bv.y - av.y) + fabsf(bv.z - av.z) + fabsf(bv.w - av.w);
        }
        if (isH) dh[r0][c0] = s; else dv[r0][c0] = s;
    }
    __syncthreads();

    if (tid < 16) {
        int r = tid; float acc = 0.f;
        g_cth[win * NTOK + r * 16 + 0] = 0.f;
        for (int c = 1; c < 16; c++) {
            acc += 1.f + sigma * dh[r][c - 1];
            g_cth[win * NTOK + r * 16 + c] = acc;
        }
    } else if (tid < 32) {
        int c = tid - 16; float acc = 0.f;
        g_ctv[win * NTOK + 0 * 16 + c] = 0.f;
        for (int r = 1; r < 16; r++) {
            acc += 1.f + sigma * dv[r - 1][c];
            g_ctv[win * NTOK + r * 16 + c] = acc;
        }
    }
}

// ---------------------------------------------------------------------------
// Kernel 2: attention via mma.sync bf16 hi/lo split (R11 version verbatim —
// measured best). 256 threads; warp = 32 q-rows; output stored bf16 hi/lo.
// ---------------------------------------------------------------------------
#define KV_STRIDE 40
#define SMEM2_BYTES (4 * 256 * KV_STRIDE * 2 + (964 + 256 + 256 + 256) * 4)

__device__ __forceinline__ const float* q_row_ptr(const float* qkv, int b, int wr, int wc,
                                                  int t, int head) {
    int i = t >> 4, j = t & 15;
    int h = wrapH(wr * WS + i), w = wrapH(wc * WS + j);
    return qkv + ((size_t)((b * HH + h) * WW + w)) * (3 * CC) + head * HD;
}

__global__ void __launch_bounds__(256) attn_kernel(const float* __restrict__ qkv,
                                                   const float* __restrict__ rpb_table,
                                                   const float* __restrict__ geo_scale) {
    extern __shared__ char smem_raw[];
    __nv_bfloat16* Kh = (__nv_bfloat16*)smem_raw;              // [256][40]
    __nv_bfloat16* Kl = Kh + 256 * KV_STRIDE;
    __nv_bfloat16* Vh = Kl + 256 * KV_STRIDE;
    __nv_bfloat16* Vl = Vh + 256 * KV_STRIDE;
    float* rpb_sh = (float*)(smem_raw + 4 * 256 * KV_STRIDE * 2);  // [961] pad 964
    float* cth_sh = rpb_sh + 964;
    float* ctv_sh = cth_sh + 256;
    int*   reg_sh = (int*)(ctv_sh + 256);

    int win = blockIdx.x, head = blockIdx.y;
    int b = win / NWB, wr = (win % NWB) / NWSIDE, wc = win % NWSIDE;
    int tid = threadIdx.x;

    // ---- fill K/V hi/lo + tables ----
    {
        int t = tid;
        int i = t >> 4, j = t & 15;
        int hs = wr * WS + i, ws = wc * WS + j;
        int h = wrapH(hs), w = wrapH(ws);
        const float* base = qkv + ((size_t)((b * HH + h) * WW + w)) * (3 * CC) + head * HD;
        const float* kp = base + CC;
        const float* vp = base + 2 * CC;
        #pragma unroll 8
        for (int d = 0; d < 32; d++) {
            float kv = kp[d];
            __nv_bfloat16 khv = __float2bfloat16(kv);
            Kh[t * KV_STRIDE + d] = khv;
            Kl[t * KV_STRIDE + d] = __float2bfloat16(kv - __bfloat162float(khv));
            float vv = vp[d];
            __nv_bfloat16 vhv = __float2bfloat16(vv);
            Vh[t * KV_STRIDE + d] = vhv;
            Vl[t * KV_STRIDE + d] = __float2bfloat16(vv - __bfloat162float(vhv));
        }
        for (int u = tid; u < 961; u += 256) rpb_sh[u] = rpb_table[u * NH + head];
        cth_sh[t] = g_cth[win * NTOK + t];
        ctv_sh[t] = g_ctv[win * NTOK + t];
        int rh  = (hs < HH - WS) ? 0 : ((hs < HH - SHIFT) ? 1 : 2);
        int rw2 = (ws < WW - WS) ? 0 : ((ws < WW - SHIFT) ? 1 : 2);
        reg_sh[t] = rh * 3 + rw2;
    }

    int warp = tid >> 5, lane = tid & 31;
    int g = lane >> 2, t4 = lane & 3;

    // ---- Q fragments straight from gmem (scale folded, hi/lo split) ----
    uint32_t qfh[2][2][4], qfl[2][2][4];
    #pragma unroll
    for (int rt = 0; rt < 2; rt++) {
        int R = warp * 32 + rt * 16;
        const float* p0 = q_row_ptr(qkv, b, wr, wc, R + g, head);
        const float* p1 = q_row_ptr(qkv, b, wr, wc, R + g + 8, head);
        #pragma unroll
        for (int ks = 0; ks < 2; ks++) {
            int kc = ks * 16 + 2 * t4;
            float2 v;
            v = *(const float2*)(p0 + kc);
            split_pack(v.x * QK_SCALE, v.y * QK_SCALE, qfh[rt][ks][0], qfl[rt][ks][0]);
            v = *(const float2*)(p1 + kc);
            split_pack(v.x * QK_SCALE, v.y * QK_SCALE, qfh[rt][ks][1], qfl[rt][ks][1]);
            v = *(const float2*)(p0 + kc + 8);
            split_pack(v.x * QK_SCALE, v.y * QK_SCALE, qfh[rt][ks][2], qfl[rt][ks][2]);
            v = *(const float2*)(p1 + kc + 8);
            split_pack(v.x * QK_SCALE, v.y * QK_SCALE, qfh[rt][ks][3], qfl[rt][ks][3]);
        }
    }
    __syncthreads();

    // ---- per-rt epilogue constants ----
    float gsc = geo_scale[head];
    float cth_q[2][2]; int myreg[2][2];
    #pragma unroll
    for (int rt = 0; rt < 2; rt++) {
        int R = warp * 32 + rt * 16;
        cth_q[rt][0] = cth_sh[R + g];     myreg[rt][0] = reg_sh[R + g];
        cth_q[rt][1] = cth_sh[R + g + 8]; myreg[rt][1] = reg_sh[R + g + 8];
    }

    float o[2][4][4];
    #pragma unroll
    for (int rt = 0; rt < 2; rt++)
        #pragma unroll
        for (int dn = 0; dn < 4; dn++)
            #pragma unroll
            for (int e = 0; e < 4; e++) o[rt][dn][e] = 0.f;
    float lsum[2][2] = {{0.f, 0.f}, {0.f, 0.f}};

    int lrow = lane & 7, lhi = (lane >> 3) & 1;

    #pragma unroll 1
    for (int T = 0; T < 8; T++) {
        int kb = T * 32;

        uint32_t kf_h[4][2][2], kf_l[4][2][2];
        #pragma unroll
        for (int nt = 0; nt < 4; nt++) {
            int row = kb + nt * 8 + lrow;
            #pragma unroll
            for (int ks = 0; ks < 2; ks++) {
                int eoff = ks * 16 + 8 * lhi;
                ldsm_x2(kf_h[nt][ks][0], kf_h[nt][ks][1], smem_u32(&Kh[row * KV_STRIDE + eoff]));
                ldsm_x2(kf_l[nt][ks][0], kf_l[nt][ks][1], smem_u32(&Kl[row * KV_STRIDE + eoff]));
            }
        }
        uint32_t vf_h[4][2][2], vf_l[4][2][2];
        #pragma unroll
        for (int kt = 0; kt < 2; kt++) {
            int key = kb + kt * 16 + lrow + 8 * lhi;
            #pragma unroll
            for (int dn = 0; dn < 4; dn++) {
                ldsm_x2_t(vf_h[dn][kt][0], vf_h[dn][kt][1], smem_u32(&Vh[key * KV_STRIDE + dn * 8]));
                ldsm_x2_t(vf_l[dn][kt][0], vf_l[dn][kt][1], smem_u32(&Vl[key * KV_STRIDE + dn * 8]));
            }
        }

        uint32_t pf_h[2][2][4], pf_l[2][2][4];
        #pragma unroll
        for (int rt = 0; rt < 2; rt++) {
            int R = warp * 32 + rt * 16;
            int rq = warp * 2 + rt;
            #pragma unroll
            for (int nt = 0; nt < 4; nt++) {
                float c[4] = {0.f, 0.f, 0.f, 0.f};
                #pragma unroll
                for (int ks = 0; ks < 2; ks++) {
                    mma_bf16(c, qfh[rt][ks], kf_h[nt][ks]);
                    mma_bf16(c, qfh[rt][ks], kf_l[nt][ks]);
                    mma_bf16(c, qfl[rt][ks], kf_h[nt][ks]);
                }
                int rk = (kb >> 4) + (nt >> 1);
                int rowoff = (rq - rk + 15) * 31 + 15;
                int ck0 = (nt & 1) * 8 + 2 * t4;
                int k0 = kb + nt * 8 + 2 * t4;

                float cthgi0 = cth_sh[R + ck0];
                float ctvgi0 = ctv_sh[R + ck0];
                float ctvk0  = ctv_sh[k0];
                int   mr0    = reg_sh[k0];
                float geo00 = fabsf(cthgi0 - cth_q[rt][0]) + fabsf(ctvk0 - ctvgi0);
                float geo01 = fabsf(cthgi0 - cth_q[rt][1]) + fabsf(ctvk0 - ctvgi0);
                float s0 = fmaf(-gsc, geo00, c[0] + rpb_sh[rowoff + g - ck0])
                         + ((myreg[rt][0] == mr0) ? 0.f : -100.f);
                float s2 = fmaf(-gsc, geo01, c[2] + rpb_sh[rowoff + g + 8 - ck0])
                         + ((myreg[rt][1] == mr0) ? 0.f : -100.f);

                float cthgi1 = cth_sh[R + ck0 + 1];
                float ctvgi1 = ctv_sh[R + ck0 + 1];
                float ctvk1  = ctv_sh[k0 + 1];
                int   mr1    = reg_sh[k0 + 1];
                float geo10 = fabsf(cthgi1 - cth_q[rt][0]) + fabsf(ctvk1 - ctvgi1);
                float geo11 = fabsf(cthgi1 - cth_q[rt][1]) + fabsf(ctvk1 - ctvgi1);
                float s1 = fmaf(-gsc, geo10, c[1] + rpb_sh[rowoff + g - ck0 - 1])
                         + ((myreg[rt][0] == mr1) ? 0.f : -100.f);
                float s3 = fmaf(-gsc, geo11, c[3] + rpb_sh[rowoff + g + 8 - ck0 - 1])
                         + ((myreg[rt][1] == mr1) ? 0.f : -100.f);

                float p0 = __expf(s0), p1 = __expf(s1);
                float p2 = __expf(s2), p3 = __expf(s3);
                lsum[rt][0] += p0 + p1;
                lsum[rt][1] += p2 + p3;

                __nv_bfloat16 h0 = __float2bfloat16(p0), h1 = __float2bfloat16(p1);
                __nv_bfloat16 h2 = __float2bfloat16(p2), h3 = __float2bfloat16(p3);
                int kt = nt >> 1, off = (nt & 1) * 2;
                __nv_bfloat162 hp01 = __halves2bfloat162(h0, h1);
                __nv_bfloat162 hp23 = __halves2bfloat162(h2, h3);
                pf_h[rt][kt][off]     = *(uint32_t*)&hp01;
                pf_h[rt][kt][off + 1] = *(uint32_t*)&hp23;
                pf_l[rt][kt][off]     = bf2(p0 - __bfloat162float(h0), p1 - __bfloat162float(h1));
                pf_l[rt][kt][off + 1] = bf2(p2 - __bfloat162float(h2), p3 - __bfloat162float(h3));
            }
        }

        #pragma unroll
        for (int rt = 0; rt < 2; rt++)
            #pragma unroll
            for (int dn = 0; dn < 4; dn++)
                #pragma unroll
                for (int kt = 0; kt < 2; kt++) {
                    mma_bf16(o[rt][dn], pf_h[rt][kt], vf_h[dn][kt]);
                    mma_bf16(o[rt][dn], pf_h[rt][kt], vf_l[dn][kt]);
                    mma_bf16(o[rt][dn], pf_l[rt][kt], vf_h[dn][kt]);
                }
    }

    #pragma unroll
    for (int rt = 0; rt < 2; rt++)
        #pragma unroll
        for (int r = 0; r < 2; r++) {
            float v = lsum[rt][r];
            v += __shfl_xor_sync(0xFFFFFFFF, v, 1);
            v += __shfl_xor_sync(0xFFFFFFFF, v, 2);
            lsum[rt][r] = v;
        }

    // normalize + store as bf16 hi/lo (tensor-ready for proj)
    #pragma unroll
    for (int rt = 0; rt < 2; rt++) {
        int R = warp * 32 + rt * 16;
        float inv0 = 1.f / lsum[rt][0];
        float inv1 = 1.f / lsum[rt][1];
        size_t i0 = (size_t)win * (NTOK * CC) + (R + g) * CC + head * HD + 2 * t4;
        size_t i1 = (size_t)win * (NTOK * CC) + (R + g + 8) * CC + head * HD + 2 * t4;
        #pragma unroll
        for (int dn = 0; dn < 4; dn++) {
            uint32_t hi, lo;
            split_pack(o[rt][dn][0] * inv0, o[rt][dn][1] * inv0, hi, lo);
            *(uint32_t*)(g_owh + i0 + dn * 8) = hi;
            *(uint32_t*)(g_owl + i0 + dn * 8) = lo;
            split_pack(o[rt][dn][2] * inv1, o[rt][dn][3] * inv1, hi, lo);
            *(uint32_t*)(g_owh + i1 + dn * 8) = hi;
            *(uint32_t*)(g_owl + i1 + dn * 8) = lo;
        }
    }
}

// ---------------------------------------------------------------------------
// Kernel 3: projection, persistent-W design.
// Grid = 148 blocks (1/SM), 512 threads = 16 warps as 4(m) x 4(n).
// Full W hi/lo resident in smem (loaded once per block); block loops over
// 64-token tiles. Zero syncs and zero staging inside the 12-chunk k loop.
// Strides: 200 halfs = 400B; 400/16 = 25 odd -> conflict-free ldmatrix.
// ---------------------------------------------------------------------------
#define AST 200
#define WRST 200
#define NPROJ_TILES (NWIN * NTOK / 64)    // 1152
#define PROJ_BLOCKS 148
#define SMEM3_BYTES ((2 * 64 * AST + 2 * CC * WRST) * 2)   // 204800 B

__global__ void __launch_bounds__(512) proj_kernel(const float* __restrict__ proj_b,
                                                   float* __restrict__ out) {
    extern __shared__ char smem3[];
    __nv_bfloat16* Ah  = (__nv_bfloat16*)smem3;        // [64][AST]
    __nv_bfloat16* Al  = Ah + 64 * AST;
    __nv_bfloat16* Wsh = Al + 64 * AST;                // [192][WRST]
    __nv_bfloat16* Wsl = Wsh + CC * WRST;              // [192][WRST]

    int t = threadIdx.x;
    int warp = t >> 5, lane = t & 31;
    int mw = warp & 3, nw = warp >> 2;                 // 4(m) x 4(n)
    int g = lane >> 2, t4 = lane & 3;
    int lg = lane >> 3;

    // ---- load full W hi/lo once (L2-resident after wprep) ----
    for (int e = t; e < CC * 96; e += 512) {
        int row = e / 96, c2 = (e % 96) * 2;
        *(uint32_t*)&Wsh[row * WRST + c2] = *(const uint32_t*)(g_Wh + row * CC + c2);
        *(uint32_t*)&Wsl[row * WRST + c2] = *(const uint32_t*)(g_Wl + row * CC + c2);
    }

    // ---- bias for this thread's 6 output pairs (tile-invariant) ----
    float2 bias[6];
    #pragma unroll
    for (int nt = 0; nt < 6; nt++) {
        int co = nw * 48 + nt * 8 + 2 * t4;
        bias[nt].x = __ldg(proj_b + co);
        bias[nt].y = __ldg(proj_b + co + 1);
    }

    // ldmatrix lane->address precompute
    int a_row = mw * 16 + (lane & 7) + (lg & 1) * 8;
    int a_col = (lg >> 1) * 8;
    int w_lrow = (lane & 7) + (lg >> 1) * 8;
    int w_col = (lg & 1) * 8;

    #pragma unroll 1
    for (int tile = blockIdx.x; tile < NPROJ_TILES; tile += PROJ_BLOCKS) {
        int tok0 = tile * 64;

        __syncthreads();   // previous tile's readers done (also orders W load, tile 0)
        for (int e = t; e < 64 * 96; e += 512) {
            int row = e / 96, c2 = (e % 96) * 2;
            size_t gidx = (size_t)(tok0 + row) * CC + c2;
            *(uint32_t*)&Ah[row * AST + c2] = *(const uint32_t*)(g_owh + gidx);
            *(uint32_t*)&Al[row * AST + c2] = *(const uint32_t*)(g_owl + gidx);
        }
        __syncthreads();

        float acc[6][4];
        #pragma unroll
        for (int nt = 0; nt < 6; nt++)
            #pragma unroll
            for (int e = 0; e < 4; e++) acc[nt][e] = 0.f;

        #pragma unroll 1
        for (int kc = 0; kc < 12; kc++) {
            uint32_t af_h[4], af_l[4];
            ldsm_x4(af_h, smem_u32(&Ah[a_row * AST + kc * 16 + a_col]));
            ldsm_x4(af_l, smem_u32(&Al[a_row * AST + kc * 16 + a_col]));

            uint32_t wf_h[6][2], wf_l[6][2];
            #pragma unroll
            for (int nt2 = 0; nt2 < 3; nt2++) {
                int nbase = nw * 48 + nt2 * 16;
                uint32_t r4[4];
                ldsm_x4(r4, smem_u32(&Wsh[(nbase + w_lrow) * WRST + kc * 16 + w_col]));
                wf_h[2 * nt2][0] = r4[0]; wf_h[2 * nt2][1] = r4[1];
                wf_h[2 * nt2 + 1][0] = r4[2]; wf_h[2 * nt2 + 1][1] = r4[3];
                ldsm_x4(r4, smem_u32(&Wsl[(nbase + w_lrow) * WRST + kc * 16 + w_col]));
                wf_l[2 * nt2][0] = r4[0]; wf_l[2 * nt2][1] = r4[1];
                wf_l[2 * nt2 + 1][0] = r4[2]; wf_l[2 * nt2 + 1][1] = r4[3];
            }

            #pragma unroll
            for (int nt = 0; nt < 6; nt++) {
                mma_bf16(acc[nt], af_h, wf_h[nt]);
                mma_bf16(acc[nt], af_h, wf_l[nt]);
                mma_bf16(acc[nt], af_l, wf_h[nt]);
            }
        }

        // Epilogue: bias + window-reverse + roll-back scatter
        #pragma unroll
        for (int half = 0; half < 2; half++) {
            int tok = tok0 + mw * 16 + g + half * 8;
            int win = tok >> 8, tt = tok & 255;
            int b = win / NWB, wr = (win % NWB) / NWSIDE, wc = win % NWSIDE;
            int i = tt >> 4, jj = tt & 15;
            int h = wrapH(wr * WS + i), w = wrapH(wc * WS + jj);
            float* op = out + ((size_t)b * (HH * WW) + h * WW + w) * CC;
            #pragma unroll
            for (int nt = 0; nt < 6; nt++) {
                int co = nw * 48 + nt * 8 + 2 * t4;
                float2 r;
                r.x = acc[nt][2 * half + 0] + bias[nt].x;
                r.y = acc[nt][2 * half + 1] + bias[nt].y;
                *(float2*)(op + co) = r;
            }
        }
    }
}

// ---------------------------------------------------------------------------
// Launch.
// ---------------------------------------------------------------------------
extern "C" void kernel_launch(void* const* d_in, const int* in_sizes, int n_in,
                              void* d_out, int out_size) {
    const float* x        = (const float*)d_in[0];
    const float* qkv      = (const float*)d_in[1];
    const float* rpb      = (const float*)d_in[2];
    const float* gscale   = (const float*)d_in[3];
    const float* gsigma   = (const float*)d_in[4];
    const float* proj_w   = (const float*)d_in[5];
    const float* proj_b   = (const float*)d_in[6];
    float* out            = (float*)d_out;

    cudaFuncSetAttribute(attn_kernel, cudaFuncAttributeMaxDynamicSharedMemorySize, SMEM2_BYTES);
    cudaFuncSetAttribute(proj_kernel, cudaFuncAttributeMaxDynamicSharedMemorySize, SMEM3_BYTES);

    wprep_kernel<<<(CC * CC + 255) / 256, 256>>>(proj_w);
    geo_kernel<<<NWIN, 256>>>(x, gsigma);
    attn_kernel<<<dim3(NWIN, NH), 256, SMEM2_BYTES>>>(qkv, rpb, gscale);
    proj_kernel<<<PROJ_BLOCKS, 512, SMEM3_BYTES>>>(proj_b, out);
}

// round 17
// speedup vs baseline: 1.4329x; 1.0529x over previous
#include <cuda_runtime.h>
#include <cuda_bf16.h>
#include <cstdint>

// Problem constants
#define BB 2
#define HH 192
#define WW 192
#define CC 192
#define WS 16
#define SHIFT 8
#define NH 6
#define HD 32
#define NTOK 256          // tokens per window
#define NWSIDE 12         // windows per side
#define NWB 144           // windows per batch
#define NWIN 288          // total windows
#define QK_SCALE 0.17677669529663687f  // 32^-0.5

// ---- mma / ldmatrix helpers ----
__device__ __forceinline__ uint32_t smem_u32(const void* p) {
    return (uint32_t)__cvta_generic_to_shared(p);
}
__device__ __forceinline__ void ldsm_x2(uint32_t& r0, uint32_t& r1, uint32_t addr) {
    asm volatile("ldmatrix.sync.aligned.m8n8.x2.shared.b16 {%0,%1}, [%2];"
                 : "=r"(r0), "=r"(r1) : "r"(addr));
}
__device__ __forceinline__ void ldsm_x2_t(uint32_t& r0, uint32_t& r1, uint32_t addr) {
    asm volatile("ldmatrix.sync.aligned.m8n8.x2.trans.shared.b16 {%0,%1}, [%2];"
                 : "=r"(r0), "=r"(r1) : "r"(addr));
}
__device__ __forceinline__ void ldsm_x4(uint32_t* r, uint32_t addr) {
    asm volatile("ldmatrix.sync.aligned.m8n8.x4.shared.b16 {%0,%1,%2,%3}, [%4];"
                 : "=r"(r[0]), "=r"(r[1]), "=r"(r[2]), "=r"(r[3]) : "r"(addr));
}
__device__ __forceinline__ void mma_bf16(float* c, const uint32_t* a, const uint32_t* b) {
    asm volatile("mma.sync.aligned.m16n8k16.row.col.f32.bf16.bf16.f32 "
                 "{%0,%1,%2,%3},{%4,%5,%6,%7},{%8,%9},{%0,%1,%2,%3};"
                 : "+f"(c[0]), "+f"(c[1]), "+f"(c[2]), "+f"(c[3])
                 : "r"(a[0]), "r"(a[1]), "r"(a[2]), "r"(a[3]), "r"(b[0]), "r"(b[1]));
}
__device__ __forceinline__ uint32_t bf2(float x, float y) {
    __nv_bfloat162 t = __floats2bfloat162_rn(x, y);   // .x = x (low half)
    return *(uint32_t*)&t;
}
__device__ __forceinline__ void split_pack(float x, float y, uint32_t& hi, uint32_t& lo) {
    __nv_bfloat16 hx = __float2bfloat16(x), hy = __float2bfloat16(y);
    __nv_bfloat162 h2 = __halves2bfloat162(hx, hy);
    hi = *(uint32_t*)&h2;
    lo = bf2(x - __bfloat162float(hx), y - __bfloat162float(hy));
}

// Scratch (static __device__ globals)
__device__ float g_cth[NWIN * NTOK];
__device__ float g_ctv[NWIN * NTOK];
__device__ __nv_bfloat16 g_owh[(size_t)NWIN * NTOK * CC];  // attn out hi
__device__ __nv_bfloat16 g_owl[(size_t)NWIN * NTOK * CC];  // attn out lo
__device__ __nv_bfloat16 g_Wh[CC * CC];                    // proj_w hi
__device__ __nv_bfloat16 g_Wl[CC * CC];                    // proj_w lo

__device__ __forceinline__ int wrapH(int hs) { int h = hs + SHIFT; return (h >= HH) ? h - HH : h; }

// ---------------------------------------------------------------------------
// Kernel 0: split proj_w into bf16 hi/lo
// ---------------------------------------------------------------------------
__global__ void __launch_bounds__(256) wprep_kernel(const float* __restrict__ proj_w) {
    int idx = blockIdx.x * 256 + threadIdx.x;
    if (idx < CC * CC) {
        float v = proj_w[idx];
        __nv_bfloat16 h = __float2bfloat16(v);
        g_Wh[idx] = h;
        g_Wl[idx] = __float2bfloat16(v - __bfloat162float(h));
    }
}

// ---------------------------------------------------------------------------
// Kernel 1: per-window geo cumulative tables cth/ctv (unchanged)
// ---------------------------------------------------------------------------
__global__ void __launch_bounds__(256) geo_kernel(const float* __restrict__ x,
                                                  const float* __restrict__ geo_sigma) {
    int win = blockIdx.x;
    int b = win / NWB, wr = (win % NWB) / NWSIDE, wc = win % NWSIDE;
    int tid = threadIdx.x;

    __shared__ float dh[16][16];
    __shared__ float dv[16][16];

    float sigma = fabsf(geo_sigma[0]);

    for (int p = tid; p < 480; p += 256) {
        int r0, c0, r1, c1; bool isH = (p < 240);
        if (isH) { int r = p / 15, j = p % 15; r0 = r; c0 = j; r1 = r; c1 = j + 1; }
        else     { int pp = p - 240; int i = pp / 16, c = pp % 16; r0 = i; c0 = c; r1 = i + 1; c1 = c; }
        int h0 = wrapH(wr * WS + r0), w0 = wrapH(wc * WS + c0);
        int h1 = wrapH(wr * WS + r1), w1 = wrapH(wc * WS + c1);
        const float* a  = x + ((size_t)((b * HH + h0) * WW + w0)) * CC;
        const float* bb = x + ((size_t)((b * HH + h1) * WW + w1)) * CC;
        float s = 0.f;
        #pragma unroll 4
        for (int ch = 0; ch < CC; ch += 4) {
            float4 av = *(const float4*)(a + ch);
            float4 bv = *(const float4*)(bb + ch);
            s += fabsf(bv.x - av.x) + fabsf(bv.y - av.y) + fabsf(bv.z - av.z) + fabsf(bv.w - av.w);
        }
        if (isH) dh[r0][c0] = s; else dv[r0][c0] = s;
    }
    __syncthreads();

    if (tid < 16) {
        int r = tid; float acc = 0.f;
        g_cth[win * NTOK + r * 16 + 0] = 0.f;
        for (int c = 1; c < 16; c++) {
            acc += 1.f + sigma * dh[r][c - 1];
            g_cth[win * NTOK + r * 16 + c] = acc;
        }
    } else if (tid < 32) {
        int c = tid - 16; float acc = 0.f;
        g_ctv[win * NTOK + 0 * 16 + c] = 0.f;
        for (int r = 1; r < 16; r++) {
            acc += 1.f + sigma * dv[r - 1][c];
            g_ctv[win * NTOK + r * 16 + c] = acc;
        }
    }
}

// ---------------------------------------------------------------------------
// Kernel 2: attention via mma.sync bf16 hi/lo split. Same math as R11 (best),
// restructured for register pressure: K/V fragments loaded at point of use,
// AV interleaved per 16-key group (pf halved). Peak live ~112 regs ->
// __launch_bounds__(256,2) gives 2 CTAs/SM (4 warps/SMSP latency cover).
// ---------------------------------------------------------------------------
#define KV_STRIDE 40
#define SMEM2_BYTES (4 * 256 * KV_STRIDE * 2 + (964 + 256 + 256 + 256) * 4)

__device__ __forceinline__ const float* q_row_ptr(const float* qkv, int b, int wr, int wc,
                                                  int t, int head) {
    int i = t >> 4, j = t & 15;
    int h = wrapH(wr * WS + i), w = wrapH(wc * WS + j);
    return qkv + ((size_t)((b * HH + h) * WW + w)) * (3 * CC) + head * HD;
}

__global__ void __launch_bounds__(256, 2) attn_kernel(const float* __restrict__ qkv,
                                                      const float* __restrict__ rpb_table,
                                                      const float* __restrict__ geo_scale) {
    extern __shared__ char smem_raw[];
    __nv_bfloat16* Kh = (__nv_bfloat16*)smem_raw;              // [256][40]
    __nv_bfloat16* Kl = Kh + 256 * KV_STRIDE;
    __nv_bfloat16* Vh = Kl + 256 * KV_STRIDE;
    __nv_bfloat16* Vl = Vh + 256 * KV_STRIDE;
    float* rpb_sh = (float*)(smem_raw + 4 * 256 * KV_STRIDE * 2);  // [961] pad 964
    float* cth_sh = rpb_sh + 964;
    float* ctv_sh = cth_sh + 256;
    int*   reg_sh = (int*)(ctv_sh + 256);

    int win = blockIdx.x, head = blockIdx.y;
    int b = win / NWB, wr = (win % NWB) / NWSIDE, wc = win % NWSIDE;
    int tid = threadIdx.x;

    // ---- fill K/V hi/lo + tables ----
    {
        int t = tid;
        int i = t >> 4, j = t & 15;
        int hs = wr * WS + i, ws = wc * WS + j;
        int h = wrapH(hs), w = wrapH(ws);
        const float* base = qkv + ((size_t)((b * HH + h) * WW + w)) * (3 * CC) + head * HD;
        const float* kp = base + CC;
        const float* vp = base + 2 * CC;
        #pragma unroll 8
        for (int d = 0; d < 32; d++) {
            float kv = kp[d];
            __nv_bfloat16 khv = __float2bfloat16(kv);
            Kh[t * KV_STRIDE + d] = khv;
            Kl[t * KV_STRIDE + d] = __float2bfloat16(kv - __bfloat162float(khv));
            float vv = vp[d];
            __nv_bfloat16 vhv = __float2bfloat16(vv);
            Vh[t * KV_STRIDE + d] = vhv;
            Vl[t * KV_STRIDE + d] = __float2bfloat16(vv - __bfloat162float(vhv));
        }
        for (int u = tid; u < 961; u += 256) rpb_sh[u] = rpb_table[u * NH + head];
        cth_sh[t] = g_cth[win * NTOK + t];
        ctv_sh[t] = g_ctv[win * NTOK + t];
        int rh  = (hs < HH - WS) ? 0 : ((hs < HH - SHIFT) ? 1 : 2);
        int rw2 = (ws < WW - WS) ? 0 : ((ws < WW - SHIFT) ? 1 : 2);
        reg_sh[t] = rh * 3 + rw2;
    }

    int warp = tid >> 5, lane = tid & 31;
    int g = lane >> 2, t4 = lane & 3;

    // ---- Q fragments straight from gmem (scale folded, hi/lo split) ----
    uint32_t qfh[2][2][4], qfl[2][2][4];
    #pragma unroll
    for (int rt = 0; rt < 2; rt++) {
        int R = warp * 32 + rt * 16;
        const float* p0 = q_row_ptr(qkv, b, wr, wc, R + g, head);
        const float* p1 = q_row_ptr(qkv, b, wr, wc, R + g + 8, head);
        #pragma unroll
        for (int ks = 0; ks < 2; ks++) {
            int kc = ks * 16 + 2 * t4;
            float2 v;
            v = *(const float2*)(p0 + kc);
            split_pack(v.x * QK_SCALE, v.y * QK_SCALE, qfh[rt][ks][0], qfl[rt][ks][0]);
            v = *(const float2*)(p1 + kc);
            split_pack(v.x * QK_SCALE, v.y * QK_SCALE, qfh[rt][ks][1], qfl[rt][ks][1]);
            v = *(const float2*)(p0 + kc + 8);
            split_pack(v.x * QK_SCALE, v.y * QK_SCALE, qfh[rt][ks][2], qfl[rt][ks][2]);
            v = *(const float2*)(p1 + kc + 8);
            split_pack(v.x * QK_SCALE, v.y * QK_SCALE, qfh[rt][ks][3], qfl[rt][ks][3]);
        }
    }
    __syncthreads();

    // ---- per-rt epilogue constants ----
    float gsc = geo_scale[head];
    float cth_q[2][2]; int myreg[2][2];
    #pragma unroll
    for (int rt = 0; rt < 2; rt++) {
        int R = warp * 32 + rt * 16;
        cth_q[rt][0] = cth_sh[R + g];     myreg[rt][0] = reg_sh[R + g];
        cth_q[rt][1] = cth_sh[R + g + 8]; myreg[rt][1] = reg_sh[R + g + 8];
    }

    float o[2][4][4];
    #pragma unroll
    for (int rt = 0; rt < 2; rt++)
        #pragma unroll
        for (int dn = 0; dn < 4; dn++)
            #pragma unroll
            for (int e = 0; e < 4; e++) o[rt][dn][e] = 0.f;
    float lsum[2][2] = {{0.f, 0.f}, {0.f, 0.f}};

    int lrow = lane & 7, lhi = (lane >> 3) & 1;

    #pragma unroll 1
    for (int T = 0; T < 8; T++) {
        int kb = T * 32;

        #pragma unroll
        for (int kt = 0; kt < 2; kt++) {
            uint32_t pf_h[2][4], pf_l[2][4];   // [rt][frag] for this 16-key group

            #pragma unroll
            for (int half = 0; half < 2; half++) {
                int nt = kt * 2 + half;
                // K fragments for this 8-key group (loaded at point of use)
                uint32_t kfh[2][2], kfl[2][2];
                int row = kb + nt * 8 + lrow;
                #pragma unroll
                for (int ks = 0; ks < 2; ks++) {
                    int eoff = ks * 16 + 8 * lhi;
                    ldsm_x2(kfh[ks][0], kfh[ks][1], smem_u32(&Kh[row * KV_STRIDE + eoff]));
                    ldsm_x2(kfl[ks][0], kfl[ks][1], smem_u32(&Kl[row * KV_STRIDE + eoff]));
                }

                #pragma unroll
                for (int rt = 0; rt < 2; rt++) {
                    int R = warp * 32 + rt * 16;
                    int rq = warp * 2 + rt;
                    float c[4] = {0.f, 0.f, 0.f, 0.f};
                    #pragma unroll
                    for (int ks = 0; ks < 2; ks++) {
                        mma_bf16(c, qfh[rt][ks], kfh[ks]);
                        mma_bf16(c, qfh[rt][ks], kfl[ks]);
                        mma_bf16(c, qfl[rt][ks], kfh[ks]);
                    }
                    int rk = (kb >> 4) + kt;
                    int rowoff = (rq - rk + 15) * 31 + 15;
                    int ck0 = half * 8 + 2 * t4;
                    int k0 = kb + nt * 8 + 2 * t4;

                    float cthgi0 = cth_sh[R + ck0];
                    float ctvgi0 = ctv_sh[R + ck0];
                    float ctvk0  = ctv_sh[k0];
                    int   mr0    = reg_sh[k0];
                    float geo00 = fabsf(cthgi0 - cth_q[rt][0]) + fabsf(ctvk0 - ctvgi0);
                    float geo01 = fabsf(cthgi0 - cth_q[rt][1]) + fabsf(ctvk0 - ctvgi0);
                    float s0 = fmaf(-gsc, geo00, c[0] + rpb_sh[rowoff + g - ck0])
                             + ((myreg[rt][0] == mr0) ? 0.f : -100.f);
                    float s2 = fmaf(-gsc, geo01, c[2] + rpb_sh[rowoff + g + 8 - ck0])
                             + ((myreg[rt][1] == mr0) ? 0.f : -100.f);

                    float cthgi1 = cth_sh[R + ck0 + 1];
                    float ctvgi1 = ctv_sh[R + ck0 + 1];
                    float ctvk1  = ctv_sh[k0 + 1];
                    int   mr1    = reg_sh[k0 + 1];
                    float geo10 = fabsf(cthgi1 - cth_q[rt][0]) + fabsf(ctvk1 - ctvgi1);
                    float geo11 = fabsf(cthgi1 - cth_q[rt][1]) + fabsf(ctvk1 - ctvgi1);
                    float s1 = fmaf(-gsc, geo10, c[1] + rpb_sh[rowoff + g - ck0 - 1])
                             + ((myreg[rt][0] == mr1) ? 0.f : -100.f);
                    float s3 = fmaf(-gsc, geo11, c[3] + rpb_sh[rowoff + g + 8 - ck0 - 1])
                             + ((myreg[rt][1] == mr1) ? 0.f : -100.f);

                    float p0 = __expf(s0), p1 = __expf(s1);
                    float p2 = __expf(s2), p3 = __expf(s3);
                    lsum[rt][0] += p0 + p1;
                    lsum[rt][1] += p2 + p3;

                    __nv_bfloat16 h0 = __float2bfloat16(p0), h1 = __float2bfloat16(p1);
                    __nv_bfloat16 h2 = __float2bfloat16(p2), h3 = __float2bfloat16(p3);
                    int off = half * 2;
                    __nv_bfloat162 hp01 = __halves2bfloat162(h0, h1);
                    __nv_bfloat162 hp23 = __halves2bfloat162(h2, h3);
                    pf_h[rt][off]     = *(uint32_t*)&hp01;
                    pf_h[rt][off + 1] = *(uint32_t*)&hp23;
                    pf_l[rt][off]     = bf2(p0 - __bfloat162float(h0), p1 - __bfloat162float(h1));
                    pf_l[rt][off + 1] = bf2(p2 - __bfloat162float(h2), p3 - __bfloat162float(h3));
                }
            }

            // AV for this 16-key group: O += Ph*Vh + Ph*Vl + Pl*Vh
            #pragma unroll
            for (int dn = 0; dn < 4; dn++) {
                int key = kb + kt * 16 + lrow + 8 * lhi;
                uint32_t vh[2], vl[2];
                ldsm_x2_t(vh[0], vh[1], smem_u32(&Vh[key * KV_STRIDE + dn * 8]));
                ldsm_x2_t(vl[0], vl[1], smem_u32(&Vl[key * KV_STRIDE + dn * 8]));
                #pragma unroll
                for (int rt = 0; rt < 2; rt++) {
                    mma_bf16(o[rt][dn], pf_h[rt], vh);
                    mma_bf16(o[rt][dn], pf_h[rt], vl);
                    mma_bf16(o[rt][dn], pf_l[rt], vh);
                }
            }
        }
    }

    #pragma unroll
    for (int rt = 0; rt < 2; rt++)
        #pragma unroll
        for (int r = 0; r < 2; r++) {
            float v = lsum[rt][r];
            v += __shfl_xor_sync(0xFFFFFFFF, v, 1);
            v += __shfl_xor_sync(0xFFFFFFFF, v, 2);
            lsum[rt][r] = v;
        }

    // normalize + store as bf16 hi/lo (tensor-ready for proj)
    #pragma unroll
    for (int rt = 0; rt < 2; rt++) {
        int R = warp * 32 + rt * 16;
        float inv0 = 1.f / lsum[rt][0];
        float inv1 = 1.f / lsum[rt][1];
        size_t i0 = (size_t)win * (NTOK * CC) + (R + g) * CC + head * HD + 2 * t4;
        size_t i1 = (size_t)win * (NTOK * CC) + (R + g + 8) * CC + head * HD + 2 * t4;
        #pragma unroll
        for (int dn = 0; dn < 4; dn++) {
            uint32_t hi, lo;
            split_pack(o[rt][dn][0] * inv0, o[rt][dn][1] * inv0, hi, lo);
            *(uint32_t*)(g_owh + i0 + dn * 8) = hi;
            *(uint32_t*)(g_owl + i0 + dn * 8) = lo;
            split_pack(o[rt][dn][2] * inv1, o[rt][dn][3] * inv1, hi, lo);
            *(uint32_t*)(g_owh + i1 + dn * 8) = hi;
            *(uint32_t*)(g_owl + i1 + dn * 8) = lo;
        }
    }
}

// ---------------------------------------------------------------------------
// Kernel 3: projection, persistent-W design (R15, measured 70us). Unchanged.
// ---------------------------------------------------------------------------
#define AST 200
#define WRST 200
#define NPROJ_TILES (NWIN * NTOK / 64)    // 1152
#define PROJ_BLOCKS 148
#define SMEM3_BYTES ((2 * 64 * AST + 2 * CC * WRST) * 2)   // 204800 B

__global__ void __launch_bounds__(512) proj_kernel(const float* __restrict__ proj_b,
                                                   float* __restrict__ out) {
    extern __shared__ char smem3[];
    __nv_bfloat16* Ah  = (__nv_bfloat16*)smem3;        // [64][AST]
    __nv_bfloat16* Al  = Ah + 64 * AST;
    __nv_bfloat16* Wsh = Al + 64 * AST;                // [192][WRST]
    __nv_bfloat16* Wsl = Wsh + CC * WRST;              // [192][WRST]

    int t = threadIdx.x;
    int warp = t >> 5, lane = t & 31;
    int mw = warp & 3, nw = warp >> 2;                 // 4(m) x 4(n)
    int g = lane >> 2, t4 = lane & 3;
    int lg = lane >> 3;

    // ---- load full W hi/lo once (L2-resident after wprep) ----
    for (int e = t; e < CC * 96; e += 512) {
        int row = e / 96, c2 = (e % 96) * 2;
        *(uint32_t*)&Wsh[row * WRST + c2] = *(const uint32_t*)(g_Wh + row * CC + c2);
        *(uint32_t*)&Wsl[row * WRST + c2] = *(const uint32_t*)(g_Wl + row * CC + c2);
    }

    // ---- bias for this thread's 6 output pairs (tile-invariant) ----
    float2 bias[6];
    #pragma unroll
    for (int nt = 0; nt < 6; nt++) {
        int co = nw * 48 + nt * 8 + 2 * t4;
        bias[nt].x = __ldg(proj_b + co);
        bias[nt].y = __ldg(proj_b + co + 1);
    }

    // ldmatrix lane->address precompute
    int a_row = mw * 16 + (lane & 7) + (lg & 1) * 8;
    int a_col = (lg >> 1) * 8;
    int w_lrow = (lane & 7) + (lg >> 1) * 8;
    int w_col = (lg & 1) * 8;

    #pragma unroll 1
    for (int tile = blockIdx.x; tile < NPROJ_TILES; tile += PROJ_BLOCKS) {
        int tok0 = tile * 64;

        __syncthreads();   // previous tile's readers done (also orders W load, tile 0)
        for (int e = t; e < 64 * 96; e += 512) {
            int row = e / 96, c2 = (e % 96) * 2;
            size_t gidx = (size_t)(tok0 + row) * CC + c2;
            *(uint32_t*)&Ah[row * AST + c2] = *(const uint32_t*)(g_owh + gidx);
            *(uint32_t*)&Al[row * AST + c2] = *(const uint32_t*)(g_owl + gidx);
        }
        __syncthreads();

        float acc[6][4];
        #pragma unroll
        for (int nt = 0; nt < 6; nt++)
            #pragma unroll
            for (int e = 0; e < 4; e++) acc[nt][e] = 0.f;

        #pragma unroll 1
        for (int kc = 0; kc < 12; kc++) {
            uint32_t af_h[4], af_l[4];
            ldsm_x4(af_h, smem_u32(&Ah[a_row * AST + kc * 16 + a_col]));
            ldsm_x4(af_l, smem_u32(&Al[a_row * AST + kc * 16 + a_col]));

            uint32_t wf_h[6][2], wf_l[6][2];
            #pragma unroll
            for (int nt2 = 0; nt2 < 3; nt2++) {
                int nbase = nw * 48 + nt2 * 16;
                uint32_t r4[4];
                ldsm_x4(r4, smem_u32(&Wsh[(nbase + w_lrow) * WRST + kc * 16 + w_col]));
                wf_h[2 * nt2][0] = r4[0]; wf_h[2 * nt2][1] = r4[1];
                wf_h[2 * nt2 + 1][0] = r4[2]; wf_h[2 * nt2 + 1][1] = r4[3];
                ldsm_x4(r4, smem_u32(&Wsl[(nbase + w_lrow) * WRST + kc * 16 + w_col]));
                wf_l[2 * nt2][0] = r4[0]; wf_l[2 * nt2][1] = r4[1];
                wf_l[2 * nt2 + 1][0] = r4[2]; wf_l[2 * nt2 + 1][1] = r4[3];
            }

            #pragma unroll
            for (int nt = 0; nt < 6; nt++) {
                mma_bf16(acc[nt], af_h, wf_h[nt]);
                mma_bf16(acc[nt], af_h, wf_l[nt]);
                mma_bf16(acc[nt], af_l, wf_h[nt]);
            }
        }

        // Epilogue: bias + window-reverse + roll-back scatter
        #pragma unroll
        for (int half = 0; half < 2; half++) {
            int tok = tok0 + mw * 16 + g + half * 8;
            int win = tok >> 8, tt = tok & 255;
            int b = win / NWB, wr = (win % NWB) / NWSIDE, wc = win % NWSIDE;
            int i = tt >> 4, jj = tt & 15;
            int h = wrapH(wr * WS + i), w = wrapH(wc * WS + jj);
            float* op = out + ((size_t)b * (HH * WW) + h * WW + w) * CC;
            #pragma unroll
            for (int nt = 0; nt < 6; nt++) {
                int co = nw * 48 + nt * 8 + 2 * t4;
                float2 r;
                r.x = acc[nt][2 * half + 0] + bias[nt].x;
                r.y = acc[nt][2 * half + 1] + bias[nt].y;
                *(float2*)(op + co) = r;
            }
        }
    }
}

// ---------------------------------------------------------------------------
// Launch.
// ---------------------------------------------------------------------------
extern "C" void kernel_launch(void* const* d_in, const int* in_sizes, int n_in,
                              void* d_out, int out_size) {
    const float* x        = (const float*)d_in[0];
    const float* qkv      = (const float*)d_in[1];
    const float* rpb      = (const float*)d_in[2];
    const float* gscale   = (const float*)d_in[3];
    const float* gsigma   = (const float*)d_in[4];
    const float* proj_w   = (const float*)d_in[5];
    const float* proj_b   = (const float*)d_in[6];
    float* out            = (float*)d_out;

    cudaFuncSetAttribute(attn_kernel, cudaFuncAttributeMaxDynamicSharedMemorySize, SMEM2_BYTES);
    cudaFuncSetAttribute(proj_kernel, cudaFuncAttributeMaxDynamicSharedMemorySize, SMEM3_BYTES);

    wprep_kernel<<<(CC * CC + 255) / 256, 256>>>(proj_w);
    geo_kernel<<<NWIN, 256>>>(x, gsigma);
    attn_kernel<<<dim3(NWIN, NH), 256, SMEM2_BYTES>>>(qkv, rpb, gscale);
    proj_kernel<<<PROJ_BLOCKS, 512, SMEM3_BYTES>>>(proj_b, out);
}